// round 1
// baseline (speedup 1.0000x reference)
#include <cuda_runtime.h>
#include <cuda_bf16.h>
#include <cstdint>

#define C_DIM 1000
#define C_VEC 250          // C_DIM / 4
#define NTHREADS 256
#define NWARPS (NTHREADS / 32)

__global__ void zero_out_kernel(float* out) {
    if (threadIdx.x == 0 && blockIdx.x == 0) out[0] = 0.0f;
}

__global__ __launch_bounds__(NTHREADS)
void ranking_loss_kernel(const float* __restrict__ logits,
                         const float* __restrict__ target,
                         float* __restrict__ out,
                         int B) {
    const int row = blockIdx.x;
    const int tid = threadIdx.x;
    const int lane = tid & 31;
    const int wid  = tid >> 5;

    const float4* tg = reinterpret_cast<const float4*>(target + (size_t)row * C_DIM);
    const float4* lg = reinterpret_cast<const float4*>(logits + (size_t)row * C_DIM);

    __shared__ float s_max[NWARPS];
    __shared__ int   s_idx[NWARPS];
    __shared__ int   s_label;
    __shared__ float s_x1;
    __shared__ float s_sum[NWARPS];

    // ---- Phase 1: argmax over target row (first-max semantics) ----
    float bmax = -3.402823466e+38f;
    int   bidx = 0x7fffffff;
    for (int i = tid; i < C_VEC; i += NTHREADS) {
        float4 v = tg[i];
        int base = i * 4;
        if (v.x > bmax || (v.x == bmax && base + 0 < bidx)) { bmax = v.x; bidx = base + 0; }
        if (v.y > bmax || (v.y == bmax && base + 1 < bidx)) { bmax = v.y; bidx = base + 1; }
        if (v.z > bmax || (v.z == bmax && base + 2 < bidx)) { bmax = v.z; bidx = base + 2; }
        if (v.w > bmax || (v.w == bmax && base + 3 < bidx)) { bmax = v.w; bidx = base + 3; }
    }
    #pragma unroll
    for (int o = 16; o > 0; o >>= 1) {
        float ov = __shfl_down_sync(0xffffffffu, bmax, o);
        int   oi = __shfl_down_sync(0xffffffffu, bidx, o);
        if (ov > bmax || (ov == bmax && oi < bidx)) { bmax = ov; bidx = oi; }
    }
    if (lane == 0) { s_max[wid] = bmax; s_idx[wid] = bidx; }
    __syncthreads();
    if (tid == 0) {
        float m = s_max[0]; int ix = s_idx[0];
        #pragma unroll
        for (int w = 1; w < NWARPS; w++) {
            if (s_max[w] > m || (s_max[w] == m && s_idx[w] < ix)) { m = s_max[w]; ix = s_idx[w]; }
        }
        s_label = ix;
        s_x1 = logits[(size_t)row * C_DIM + ix];
    }
    __syncthreads();

    const int   label = s_label;
    const float x1    = s_x1;
    const float inv   = 1.0f / (float)(C_DIM - 1);

    // ---- Phase 2: hinge sum over logits row ----
    // margin(0) = 1.0 (neg term, NEG_MARGIN=1 folds in exactly),
    // margin(j) = |label - j| / (C-1) for j>=1.
    float acc = 0.0f;
    for (int i = tid; i < C_VEC; i += NTHREADS) {
        float4 v = lg[i];
        int base = i * 4;
        {
            int j = base + 0;
            float margin = (j == 0) ? 1.0f : (float)abs(label - j) * inv;
            acc += fmaxf(0.0f, v.x - x1 + margin);
        }
        {
            int j = base + 1;
            float margin = (float)abs(label - j) * inv;
            acc += fmaxf(0.0f, v.y - x1 + margin);
        }
        {
            int j = base + 2;
            float margin = (float)abs(label - j) * inv;
            acc += fmaxf(0.0f, v.z - x1 + margin);
        }
        {
            int j = base + 3;
            float margin = (float)abs(label - j) * inv;
            acc += fmaxf(0.0f, v.w - x1 + margin);
        }
    }
    #pragma unroll
    for (int o = 16; o > 0; o >>= 1)
        acc += __shfl_down_sync(0xffffffffu, acc, o);
    if (lane == 0) s_sum[wid] = acc;
    __syncthreads();
    if (tid == 0) {
        float total = 0.0f;
        #pragma unroll
        for (int w = 0; w < NWARPS; w++) total += s_sum[w];
        if (label != 0)
            atomicAdd(out, total * (1.0f / (float)B));
    }
}

extern "C" void kernel_launch(void* const* d_in, const int* in_sizes, int n_in,
                              void* d_out, int out_size) {
    const float* logits = (const float*)d_in[0];
    const float* target = (const float*)d_in[1];
    float* out = (float*)d_out;
    const int B = in_sizes[0] / C_DIM;   // 16384

    zero_out_kernel<<<1, 32>>>(out);
    ranking_loss_kernel<<<B, NTHREADS>>>(logits, target, out, B);
}

// round 3
// speedup vs baseline: 1.5283x; 1.5283x over previous
#include <cuda_runtime.h>
#include <cuda_bf16.h>
#include <cstdint>

#define C_DIM 1000
#define C_VEC 250            // C_DIM / 4
#define VPT 8                // ceil(C_VEC / 32)
#define ROWS_PER_CTA 8
#define NTHREADS (ROWS_PER_CTA * 32)

__device__ float        g_scratch = 0.0f;
__device__ unsigned int g_count   = 0;

__global__ __launch_bounds__(NTHREADS)
void ranking_loss_kernel(const float* __restrict__ logits,
                         const float* __restrict__ target,
                         float* __restrict__ out,
                         int B) {
    const int lane = threadIdx.x & 31;
    const int wid  = threadIdx.x >> 5;
    const int row  = blockIdx.x * ROWS_PER_CTA + wid;

    const float4* tg = reinterpret_cast<const float4*>(target + (size_t)row * C_DIM);
    const float4* lg = reinterpret_cast<const float4*>(logits + (size_t)row * C_DIM);

    const float NEG_INF = -3.402823466e+38f;

    // ---- Load target vecs (8 per lane, strided; front-batched -> MLP_p1=8) ----
    float4 t[VPT];
    #pragma unroll
    for (int k = 0; k < VPT; k++) {
        int v = lane + 32 * k;
        if (v < C_VEC) t[k] = tg[v];
        else           t[k] = make_float4(NEG_INF, NEG_INF, NEG_INF, NEG_INF);
    }

    // ---- Local argmax (first-max semantics) ----
    float bmax = NEG_INF;
    int   bidx = 0x7fffffff;
    #pragma unroll
    for (int k = 0; k < VPT; k++) {
        int base = (lane + 32 * k) * 4;
        if (t[k].x > bmax) { bmax = t[k].x; bidx = base + 0; }
        if (t[k].y > bmax) { bmax = t[k].y; bidx = base + 1; }
        if (t[k].z > bmax) { bmax = t[k].z; bidx = base + 2; }
        if (t[k].w > bmax) { bmax = t[k].w; bidx = base + 3; }
    }

    // ---- Issue logits loads NOW so DRAM latency hides behind the reduce ----
    float4 l[VPT];
    #pragma unroll
    for (int k = 0; k < VPT; k++) {
        int v = lane + 32 * k;
        if (v < C_VEC) l[k] = lg[v];
        else           l[k] = make_float4(NEG_INF, NEG_INF, NEG_INF, NEG_INF); // guarded out below
    }

    // ---- Warp argmax reduce (butterfly; (max, min-index) is assoc+comm) ----
    #pragma unroll
    for (int o = 16; o > 0; o >>= 1) {
        float ov = __shfl_xor_sync(0xffffffffu, bmax, o);
        int   oi = __shfl_xor_sync(0xffffffffu, bidx, o);
        if (ov > bmax || (ov == bmax && oi < bidx)) { bmax = ov; bidx = oi; }
    }
    const int label = bidx;

    // x1: uniform per-warp load; line is L1-resident from the scan above
    const float x1 = logits[(size_t)row * C_DIM + label];

    const float inv = 1.0f / (float)(C_DIM - 1);
    const float labf = (float)label;

    // ---- Hinge sum. margin(0)=1.0 (neg term, NEG_MARGIN=1 folds in),
    //      margin(j)=|label-j|/(C-1) for j>=1. ----
    float acc = 0.0f;
    #pragma unroll
    for (int k = 0; k < VPT; k++) {
        int v = lane + 32 * k;
        if (v < C_VEC) {
            float jf = (float)(v * 4);
            float m0 = (v == 0 && lane == 0) ? 1.0f : fabsf(labf - jf) * inv;
            float m1 = fabsf(labf - (jf + 1.0f)) * inv;
            float m2 = fabsf(labf - (jf + 2.0f)) * inv;
            float m3 = fabsf(labf - (jf + 3.0f)) * inv;
            acc += fmaxf(0.0f, l[k].x - x1 + m0);
            acc += fmaxf(0.0f, l[k].y - x1 + m1);
            acc += fmaxf(0.0f, l[k].z - x1 + m2);
            acc += fmaxf(0.0f, l[k].w - x1 + m3);
        }
    }

    // ---- Warp sum reduce ----
    #pragma unroll
    for (int o = 16; o > 0; o >>= 1)
        acc += __shfl_xor_sync(0xffffffffu, acc, o);

    // per-row contribution (zero when label == 0), pre-scaled by 1/B
    float row_val = (label != 0) ? acc * (1.0f / (float)B) : 0.0f;

    // ---- CTA partial reduce in smem, single atomic per CTA ----
    __shared__ float s_sum[ROWS_PER_CTA];
    if (lane == 0) s_sum[wid] = row_val;
    __syncthreads();

    if (threadIdx.x == 0) {
        float cta = 0.0f;
        #pragma unroll
        for (int w = 0; w < ROWS_PER_CTA; w++) cta += s_sum[w];
        atomicAdd(&g_scratch, cta);
        __threadfence();
        unsigned int done = atomicAdd(&g_count, 1u);
        if (done == gridDim.x - 1) {
            // last CTA: all prior g_scratch adds are visible (fence+count order)
            float total = *((volatile float*)&g_scratch);
            out[0] = total;
            g_scratch = 0.0f;   // reset for next graph replay
            g_count   = 0u;
            __threadfence();
        }
    }
}

extern "C" void kernel_launch(void* const* d_in, const int* in_sizes, int n_in,
                              void* d_out, int out_size) {
    const float* logits = (const float*)d_in[0];
    const float* target = (const float*)d_in[1];
    float* out = (float*)d_out;
    const int B = in_sizes[0] / C_DIM;       // 16384
    const int grid = B / ROWS_PER_CTA;       // 2048

    ranking_loss_kernel<<<grid, NTHREADS>>>(logits, target, out, B);
}